// round 1
// baseline (speedup 1.0000x reference)
#include <cuda_runtime.h>
#include <math.h>

// Problem constants
#define BATCH   16
#define HH      64
#define WW      64
#define CC      192
#define NHEAD   6
#define WSZ     8
#define NTOK    64            // tokens per window
#define HD      32            // head dim
#define NWIN    64            // windows per image
#define MROWS   (BATCH*HH*WW) // 65536 total tokens
#define QKVDIM  (3*CC)        // 576
#define MLPDIM  (4*CC)        // 768
#define SCALE_Q 0.17677669529663687f  // 32^-0.5

// Scratch (device globals: allocation-free per harness rules)
__device__ float g_win [(size_t)MROWS * CC];      // LN output / windowed activations (50 MB)
__device__ float g_big [(size_t)MROWS * MLPDIM];  // qkv (576 cols) & mlp hidden (768 cols) (201 MB)
__device__ float g_o   [(size_t)MROWS * CC];      // attention output (50 MB)

// ---------------------------------------------------------------------------
// LayerNorm (+ optional shift + window partition). One warp per output row.
// windowed=1: out row r is window-token order; source pixel = shifted image pos
// ---------------------------------------------------------------------------
__global__ __launch_bounds__(256) void ln_kernel(
    const float* __restrict__ x, const float* __restrict__ gam,
    const float* __restrict__ bet, float* __restrict__ out,
    int shift, int windowed)
{
    int warp = threadIdx.x >> 5, lane = threadIdx.x & 31;
    int r = blockIdx.x * 8 + warp;
    int src;
    if (windowed) {
        int bw = r >> 6, tok = r & 63;
        int b_img = bw >> 6, wr = (bw >> 3) & 7, wc = bw & 7;
        int ti = tok >> 3, tj = tok & 7;
        int h = (wr * 8 + ti + shift) & 63;
        int w = (wc * 8 + tj + shift) & 63;
        src = b_img * 4096 + h * 64 + w;
    } else {
        src = r;
    }
    const float* xp = x + (size_t)src * CC;
    float v[6];
    float s = 0.f;
#pragma unroll
    for (int j = 0; j < 6; j++) { v[j] = xp[lane + 32 * j]; s += v[j]; }
#pragma unroll
    for (int o = 16; o; o >>= 1) s += __shfl_xor_sync(0xffffffffu, s, o);
    float mu = s * (1.f / 192.f);
    float q = 0.f;
#pragma unroll
    for (int j = 0; j < 6; j++) { float d = v[j] - mu; q += d * d; }
#pragma unroll
    for (int o = 16; o; o >>= 1) q += __shfl_xor_sync(0xffffffffu, q, o);
    float rstd = rsqrtf(q * (1.f / 192.f) + 1e-5f);
    float* op = out + (size_t)r * CC;
#pragma unroll
    for (int j = 0; j < 6; j++) {
        int c = lane + 32 * j;
        op[c] = (v[j] - mu) * rstd * gam[c] + bet[c];
    }
}

// ---------------------------------------------------------------------------
// Tiled SGEMM: C = A[M,K] @ W[N,K]^T + bias, with epilogue modes.
// BM=128, BN=64, BK=16, 256 threads, 8x4 microtile.
// ---------------------------------------------------------------------------
#define BM 128
#define BN 64
#define BK 16

#define MODE_STORE  0
#define MODE_GELU   1
#define MODE_RESADD 2
#define MODE_PROJ   3   // window-reverse + unshift + residual add

template<int MODE>
__global__ __launch_bounds__(256) void gemm_kernel(
    const float* __restrict__ A, const float* __restrict__ W,
    const float* __restrict__ bias, float* __restrict__ Cp,
    int N, int K, int shift)
{
    __shared__ float As[BK][BM];
    __shared__ float Bs[BK][BN];
    int tid = threadIdx.x;
    int m0 = blockIdx.y * BM;
    int n0 = blockIdx.x * BN;

    int arow = tid >> 1, acol = (tid & 1) * 8;
    int brow = tid >> 2, bcol = (tid & 3) * 4;
    const float* Ap = A + (size_t)(m0 + arow) * K + acol;
    const float* Wp = W + (size_t)(n0 + brow) * K + bcol;

    int tx = tid & 15, ty = tid >> 4;

    float acc[8][4];
#pragma unroll
    for (int i = 0; i < 8; i++)
#pragma unroll
        for (int j = 0; j < 4; j++) acc[i][j] = 0.f;

    for (int k0 = 0; k0 < K; k0 += BK) {
        float4 a0 = *(const float4*)(Ap + k0);
        float4 a1 = *(const float4*)(Ap + k0 + 4);
        float4 b0 = *(const float4*)(Wp + k0);
        __syncthreads();
        As[acol + 0][arow] = a0.x; As[acol + 1][arow] = a0.y;
        As[acol + 2][arow] = a0.z; As[acol + 3][arow] = a0.w;
        As[acol + 4][arow] = a1.x; As[acol + 5][arow] = a1.y;
        As[acol + 6][arow] = a1.z; As[acol + 7][arow] = a1.w;
        Bs[bcol + 0][brow] = b0.x; Bs[bcol + 1][brow] = b0.y;
        Bs[bcol + 2][brow] = b0.z; Bs[bcol + 3][brow] = b0.w;
        __syncthreads();
#pragma unroll
        for (int kk = 0; kk < BK; kk++) {
            float4 af0 = *(const float4*)&As[kk][ty * 8];
            float4 af1 = *(const float4*)&As[kk][ty * 8 + 4];
            float4 bf  = *(const float4*)&Bs[kk][tx * 4];
            float a[8] = {af0.x, af0.y, af0.z, af0.w, af1.x, af1.y, af1.z, af1.w};
            float b[4] = {bf.x, bf.y, bf.z, bf.w};
#pragma unroll
            for (int i = 0; i < 8; i++)
#pragma unroll
                for (int j = 0; j < 4; j++)
                    acc[i][j] += a[i] * b[j];
        }
    }

#pragma unroll
    for (int i = 0; i < 8; i++) {
        int row = m0 + ty * 8 + i;
        int dest = row;
        if (MODE == MODE_PROJ) {
            int bw = row >> 6, tok = row & 63;
            int b_img = bw >> 6, wr = (bw >> 3) & 7, wc = bw & 7;
            int ti = tok >> 3, tj = tok & 7;
            int h = (wr * 8 + ti + shift) & 63;
            int w = (wc * 8 + tj + shift) & 63;
            dest = b_img * 4096 + h * 64 + w;
        }
#pragma unroll
        for (int j = 0; j < 4; j++) {
            int col = n0 + tx * 4 + j;
            float v = acc[i][j] + bias[col];
            if (MODE == MODE_GELU)
                v = 0.5f * v * (1.f + erff(v * 0.70710678118654752f));
            if (MODE == MODE_STORE || MODE == MODE_GELU)
                Cp[(size_t)row * N + col] = v;
            else if (MODE == MODE_RESADD)
                Cp[(size_t)row * N + col] += v;
            else // MODE_PROJ
                Cp[(size_t)dest * CC + col] += v;
        }
    }
}

// ---------------------------------------------------------------------------
// Fused windowed attention: one block (64 threads) per (head, window).
// scores + rel-pos-bias + shift-mask + softmax + PV in smem/registers.
// qkv layout: [bw, n, s*192 + head*32 + d]
// ---------------------------------------------------------------------------
__global__ __launch_bounds__(64) void attn_kernel(
    const float* __restrict__ qkv, const float* __restrict__ tbl,
    float* __restrict__ o, int shift)
{
    __shared__ float ks[64][32];
    __shared__ float vs[64][32];
    __shared__ float tbl_s[225];
    __shared__ int   rid_s[64];

    int head = blockIdx.x;
    int bw   = blockIdx.y;
    int tid  = threadIdx.x;

    const float* base = qkv + (size_t)bw * NTOK * QKVDIM;
#pragma unroll
    for (int idx = tid; idx < 2048; idx += 64) {
        int m = idx >> 5, d = idx & 31;
        ks[m][d] = base[m * QKVDIM + 192 + head * 32 + d];
        vs[m][d] = base[m * QKVDIM + 384 + head * 32 + d];
    }
    for (int idx = tid; idx < 225; idx += 64)
        tbl_s[idx] = tbl[idx * NHEAD + head];
    {
        int wr = (bw >> 3) & 7, wc = bw & 7;
        int ti = tid >> 3, tj = tid & 7;
        int h = wr * 8 + ti, w = wc * 8 + tj;
        int rh = (h < 56) ? 0 : ((h < 60) ? 1 : 2);
        int rw = (w < 56) ? 0 : ((w < 60) ? 1 : 2);
        rid_s[tid] = rh * 3 + rw;
    }
    __syncthreads();

    int n = tid;
    float qv[32];
    const float* qp = base + n * QKVDIM + head * 32;
#pragma unroll
    for (int d = 0; d < 32; d++) qv[d] = qp[d] * SCALE_Q;

    int ni = n >> 3, nj = n & 7;
    int myid = rid_s[n];

    float s[64];
    float mx = -1e30f;
#pragma unroll
    for (int m = 0; m < 64; m++) {
        float dot = 0.f;
#pragma unroll
        for (int d = 0; d < 32; d += 4) {
            float4 kk = *(const float4*)&ks[m][d];
            dot += qv[d] * kk.x + qv[d + 1] * kk.y + qv[d + 2] * kk.z + qv[d + 3] * kk.w;
        }
        int mi = m >> 3, mj = m & 7;
        float val = dot + tbl_s[(ni - mi + 7) * 15 + (nj - mj + 7)];
        if (shift && rid_s[m] != myid) val -= 100.f;
        s[m] = val;
        mx = fmaxf(mx, val);
    }

    float sum = 0.f;
    float accv[32];
#pragma unroll
    for (int d = 0; d < 32; d++) accv[d] = 0.f;
#pragma unroll
    for (int m = 0; m < 64; m++) {
        float e = __expf(s[m] - mx);
        sum += e;
#pragma unroll
        for (int d = 0; d < 32; d += 4) {
            float4 vv = *(const float4*)&vs[m][d];
            accv[d]     += e * vv.x;
            accv[d + 1] += e * vv.y;
            accv[d + 2] += e * vv.z;
            accv[d + 3] += e * vv.w;
        }
    }
    float inv = 1.f / sum;
    float* op = o + (size_t)bw * NTOK * CC + n * CC + head * 32;
#pragma unroll
    for (int d = 0; d < 32; d++) op[d] = accv[d] * inv;
}

// ---------------------------------------------------------------------------
// Launch
// ---------------------------------------------------------------------------
extern "C" void kernel_launch(void* const* d_in, const int* in_sizes, int n_in,
                              void* d_out, int out_size)
{
    const float* x    = (const float*)d_in[0];
    const float* n1g  = (const float*)d_in[1];
    const float* n1b  = (const float*)d_in[2];
    const float* qkvw = (const float*)d_in[3];
    const float* qkvb = (const float*)d_in[4];
    const float* tbl  = (const float*)d_in[5];
    const float* pw   = (const float*)d_in[6];
    const float* pb   = (const float*)d_in[7];
    const float* n2g  = (const float*)d_in[8];
    const float* n2b  = (const float*)d_in[9];
    const float* f1w  = (const float*)d_in[10];
    const float* f1b  = (const float*)d_in[11];
    const float* f2w  = (const float*)d_in[12];
    const float* f2b  = (const float*)d_in[13];
    float* xo = (float*)d_out;

    float *win, *big, *obuf;
    cudaGetSymbolAddress((void**)&win,  g_win);
    cudaGetSymbolAddress((void**)&big,  g_big);
    cudaGetSymbolAddress((void**)&obuf, g_o);

    cudaMemcpyAsync(xo, x, (size_t)MROWS * CC * sizeof(float),
                    cudaMemcpyDeviceToDevice);

    for (int dep = 0; dep < 2; dep++) {
        int shift = dep ? 4 : 0;

        // LN1 + shift + window partition
        ln_kernel<<<MROWS / 8, 256>>>(xo, n1g + dep * CC, n1b + dep * CC, win, shift, 1);

        // QKV GEMM: [65536,192] x [576,192]^T
        gemm_kernel<MODE_STORE><<<dim3(QKVDIM / BN, MROWS / BM), 256>>>(
            win, qkvw + (size_t)dep * QKVDIM * CC, qkvb + dep * QKVDIM, big,
            QKVDIM, CC, 0);

        // Fused attention
        attn_kernel<<<dim3(NHEAD, BATCH * NWIN), 64>>>(
            big, tbl + dep * 225 * NHEAD, obuf, shift);

        // Proj GEMM + window reverse + unshift + residual add into x
        gemm_kernel<MODE_PROJ><<<dim3(CC / BN, MROWS / BM), 256>>>(
            obuf, pw + (size_t)dep * CC * CC, pb + dep * CC, xo,
            CC, CC, shift);

        // LN2 (plain)
        ln_kernel<<<MROWS / 8, 256>>>(xo, n2g + dep * CC, n2b + dep * CC, win, 0, 0);

        // FC1 GEMM + exact GELU
        gemm_kernel<MODE_GELU><<<dim3(MLPDIM / BN, MROWS / BM), 256>>>(
            win, f1w + (size_t)dep * MLPDIM * CC, f1b + dep * MLPDIM, big,
            MLPDIM, CC, 0);

        // FC2 GEMM + residual add into x
        gemm_kernel<MODE_RESADD><<<dim3(CC / BN, MROWS / BM), 256>>>(
            big, f2w + (size_t)dep * CC * MLPDIM, f2b + dep * CC, xo,
            CC, MLPDIM, 0);
    }
}

// round 3
// speedup vs baseline: 1.8033x; 1.8033x over previous
#include <cuda_runtime.h>
#include <cuda_fp16.h>
#include <cstdint>
#include <math.h>

// Problem constants
#define BATCH   16
#define CC      192
#define NHEAD   6
#define NTOK    64
#define NWIN    64
#define MROWS   65536
#define QKVDIM  576
#define MLPDIM  768
#define SCALE_Q 0.17677669529663687f

// Weight half-buffer offsets (elements), layout [qkv2, proj2, fc12, fc22]
#define WOFF_QKV  0
#define WOFF_PROJ 221184
#define WOFF_FC1  294912
#define WOFF_FC2  589824
#define WTOTAL    884736

// Scratch (device globals)
__device__ __half g_ah[(size_t)MROWS * 192];
__device__ __half g_al[(size_t)MROWS * 192];
__device__ __half g_bh[(size_t)MROWS * 768];
__device__ __half g_bl[(size_t)MROWS * 768];
__device__ float  g_big[(size_t)MROWS * 576];
__device__ __half g_wh[WTOTAL];
__device__ __half g_wl[WTOTAL];

// ---------------------------------------------------------------------------
// PTX helpers (baseline sm_103-compatible: mma.sync / ldmatrix / cp.async)
// ---------------------------------------------------------------------------
__device__ __forceinline__ uint32_t smem_u32(const void* p) {
    uint32_t a;
    asm("{ .reg .u64 t; cvta.to.shared.u64 t, %1; cvt.u32.u64 %0, t; }"
        : "=r"(a) : "l"(p));
    return a;
}

#define CP16(dst, src) \
    asm volatile("cp.async.cg.shared.global [%0], [%1], 16;" :: "r"(dst), "l"(src))

#define LDSM4(r0, r1, r2, r3, addr) \
    asm volatile("ldmatrix.sync.aligned.m8n8.x4.shared.b16 {%0,%1,%2,%3}, [%4];" \
        : "=r"(r0), "=r"(r1), "=r"(r2), "=r"(r3) : "r"(addr))

#define MMA16816(d, a, b0, b1) \
    asm volatile("mma.sync.aligned.m16n8k16.row.col.f32.f16.f16.f32 " \
        "{%0,%1,%2,%3},{%4,%5,%6,%7},{%8,%9},{%0,%1,%2,%3};" \
        : "+f"((d)[0]), "+f"((d)[1]), "+f"((d)[2]), "+f"((d)[3]) \
        : "r"((a)[0]), "r"((a)[1]), "r"((a)[2]), "r"((a)[3]), "r"(b0), "r"(b1))

// ---------------------------------------------------------------------------
// Weight conversion: fp32 -> (hi, lo) fp16
// ---------------------------------------------------------------------------
__global__ __launch_bounds__(256) void cvt_kernel(
    const float* __restrict__ src, __half* __restrict__ h,
    __half* __restrict__ l, int n)
{
    int i = blockIdx.x * 256 + threadIdx.x;
    if (i < n) {
        float x = src[i];
        __half hh = __float2half(x);
        h[i] = hh;
        l[i] = __float2half(x - __half2float(hh));
    }
}

// ---------------------------------------------------------------------------
// LayerNorm (+ optional shift + window partition), outputs hi/lo fp16
// ---------------------------------------------------------------------------
__global__ __launch_bounds__(256) void ln_kernel(
    const float* __restrict__ x, const float* __restrict__ gam,
    const float* __restrict__ bet, __half* __restrict__ oh,
    __half* __restrict__ ol, int shift, int windowed)
{
    int warp = threadIdx.x >> 5, lane = threadIdx.x & 31;
    int r = blockIdx.x * 8 + warp;
    int src;
    if (windowed) {
        int bw = r >> 6, tok = r & 63;
        int b_img = bw >> 6, wr = (bw >> 3) & 7, wc = bw & 7;
        int ti = tok >> 3, tj = tok & 7;
        int h = (wr * 8 + ti + shift) & 63;
        int w = (wc * 8 + tj + shift) & 63;
        src = b_img * 4096 + h * 64 + w;
    } else src = r;
    const float* xp = x + (size_t)src * CC;
    float v[6];
    float s = 0.f;
#pragma unroll
    for (int j = 0; j < 6; j++) { v[j] = xp[lane + 32 * j]; s += v[j]; }
#pragma unroll
    for (int o = 16; o; o >>= 1) s += __shfl_xor_sync(0xffffffffu, s, o);
    float mu = s * (1.f / 192.f);
    float q = 0.f;
#pragma unroll
    for (int j = 0; j < 6; j++) { float d = v[j] - mu; q += d * d; }
#pragma unroll
    for (int o = 16; o; o >>= 1) q += __shfl_xor_sync(0xffffffffu, q, o);
    float rstd = rsqrtf(q * (1.f / 192.f) + 1e-5f);
    size_t base = (size_t)r * CC;
#pragma unroll
    for (int j = 0; j < 6; j++) {
        int c = lane + 32 * j;
        float y = (v[j] - mu) * rstd * gam[c] + bet[c];
        __half hh = __float2half(y);
        oh[base + c] = hh;
        ol[base + c] = __float2half(y - __half2float(hh));
    }
}

// ---------------------------------------------------------------------------
// fp16-split tensor-core GEMM: C[M,N] = A[M,K] @ W[N,K]^T + bias
// BM=128, BN=64, BK=64, 256 threads (8 warps, 4x2), warp tile 32x32.
// 2-stage cp.async pipeline, XOR-swizzled smem, ldmatrix + mma.m16n8k16.
// ---------------------------------------------------------------------------
#define MODE_STORE   0
#define MODE_GELU_HL 1
#define MODE_RESADD  2
#define MODE_PROJ    3

#define STAGE_BYTES 49152   // Ah 16K + Al 16K + Bh 8K + Bl 8K
#define GEMM_SMEM   (2 * STAGE_BYTES)

template<int MODE>
__global__ __launch_bounds__(256) void gemm_mma(
    const __half* __restrict__ Ah, const __half* __restrict__ Al,
    const __half* __restrict__ Bh, const __half* __restrict__ Bl,
    const float* __restrict__ bias, float* __restrict__ Cp,
    __half* __restrict__ Oh, __half* __restrict__ Ol,
    int N, int K, int shift)
{
    extern __shared__ char smem[];
    const uint32_t smbase = smem_u32(smem);
    const int tid  = threadIdx.x;
    const int lane = tid & 31, warp = tid >> 5;
    const int wm = warp >> 1, wn = warp & 1;
    const int m0 = blockIdx.y * 128, n0 = blockIdx.x * 64;
    const int lc = tid & 7;           // chunk col for loads
    const int lr = tid >> 3;          // base row for loads

    const __half* pAh = Ah + (size_t)m0 * K + lc * 8;
    const __half* pAl = Al + (size_t)m0 * K + lc * 8;
    const __half* pBh = Bh + (size_t)n0 * K + lc * 8;
    const __half* pBl = Bl + (size_t)n0 * K + lc * 8;

    const int niter = K >> 6;

    auto issue = [&](int s) {
        uint32_t sb = smbase + (uint32_t)(s & 1) * STAGE_BYTES;
        int k0 = s << 6;
#pragma unroll
        for (int i = 0; i < 4; i++) {
            int r = lr + 32 * i;
            uint32_t d = sb + r * 128 + ((uint32_t)(lc ^ (r & 7)) << 4);
            CP16(d,         pAh + (size_t)r * K + k0);
            CP16(d + 16384, pAl + (size_t)r * K + k0);
        }
#pragma unroll
        for (int i = 0; i < 2; i++) {
            int r = lr + 32 * i;
            uint32_t d = sb + 32768 + r * 128 + ((uint32_t)(lc ^ (r & 7)) << 4);
            CP16(d,        pBh + (size_t)r * K + k0);
            CP16(d + 8192, pBl + (size_t)r * K + k0);
        }
        asm volatile("cp.async.commit_group;");
    };

    float acc[2][4][4];
#pragma unroll
    for (int i = 0; i < 2; i++)
#pragma unroll
        for (int j = 0; j < 4; j++)
#pragma unroll
            for (int e = 0; e < 4; e++) acc[i][j][e] = 0.f;

    issue(0);
    for (int s = 0; s < niter; s++) {
        if (s + 1 < niter) {
            issue(s + 1);
            asm volatile("cp.async.wait_group 1;");
        } else {
            asm volatile("cp.async.wait_group 0;");
        }
        __syncthreads();
        uint32_t sb = smbase + (uint32_t)(s & 1) * STAGE_BYTES;
#pragma unroll
        for (int kk = 0; kk < 4; kk++) {
            uint32_t aH[2][4], aL[2][4], bH[2][4], bL[2][4];
#pragma unroll
            for (int i = 0; i < 2; i++) {
                int r  = wm * 32 + i * 16 + (lane & 15);
                int ch = kk * 2 + (lane >> 4);
                uint32_t ad = sb + r * 128 + ((uint32_t)(ch ^ (r & 7)) << 4);
                LDSM4(aH[i][0], aH[i][1], aH[i][2], aH[i][3], ad);
                LDSM4(aL[i][0], aL[i][1], aL[i][2], aL[i][3], ad + 16384);
            }
#pragma unroll
            for (int i = 0; i < 2; i++) {
                int grp = lane >> 3;
                int r  = wn * 32 + i * 16 + ((grp >> 1) << 3) + (lane & 7);
                int ch = kk * 2 + (grp & 1);
                uint32_t bd = sb + 32768 + r * 128 + ((uint32_t)(ch ^ (r & 7)) << 4);
                LDSM4(bH[i][0], bH[i][1], bH[i][2], bH[i][3], bd);
                LDSM4(bL[i][0], bL[i][1], bL[i][2], bL[i][3], bd + 8192);
            }
#pragma unroll
            for (int i = 0; i < 2; i++)
#pragma unroll
                for (int jj = 0; jj < 4; jj++) {
                    int bi = jj >> 1, bo = (jj & 1) * 2;
                    MMA16816(acc[i][jj], aH[i], bH[bi][bo], bH[bi][bo + 1]);
                    MMA16816(acc[i][jj], aH[i], bL[bi][bo], bL[bi][bo + 1]);
                    MMA16816(acc[i][jj], aL[i], bH[bi][bo], bH[bi][bo + 1]);
                }
        }
        __syncthreads();
    }

    // epilogue
#pragma unroll
    for (int i = 0; i < 2; i++) {
        int rb = m0 + wm * 32 + i * 16 + (lane >> 2);
#pragma unroll
        for (int hf = 0; hf < 2; hf++) {
            int r = rb + hf * 8;
            int dest = r;
            if (MODE == MODE_PROJ) {
                int bw = r >> 6, tok = r & 63;
                int b_img = bw >> 6, wr = (bw >> 3) & 7, wc = bw & 7;
                int ti = tok >> 3, tj = tok & 7;
                int h = (wr * 8 + ti + shift) & 63;
                int w = (wc * 8 + tj + shift) & 63;
                dest = b_img * 4096 + h * 64 + w;
            }
#pragma unroll
            for (int jj = 0; jj < 4; jj++) {
                int c = n0 + wn * 32 + jj * 8 + (lane & 3) * 2;
                float v0 = acc[i][jj][hf * 2 + 0] + bias[c];
                float v1 = acc[i][jj][hf * 2 + 1] + bias[c + 1];
                if (MODE == MODE_STORE) {
                    float2 o = make_float2(v0, v1);
                    *(float2*)(Cp + (size_t)r * N + c) = o;
                } else if (MODE == MODE_GELU_HL) {
                    float g0 = 0.5f * v0 * (1.f + erff(v0 * 0.70710678118654752f));
                    float g1 = 0.5f * v1 * (1.f + erff(v1 * 0.70710678118654752f));
                    __half h0 = __float2half(g0), h1 = __float2half(g1);
                    __half l0 = __float2half(g0 - __half2float(h0));
                    __half l1 = __float2half(g1 - __half2float(h1));
                    *(__half2*)(Oh + (size_t)r * N + c) = __halves2half2(h0, h1);
                    *(__half2*)(Ol + (size_t)r * N + c) = __halves2half2(l0, l1);
                } else if (MODE == MODE_RESADD) {
                    float2* p = (float2*)(Cp + (size_t)r * N + c);
                    float2 o = *p; o.x += v0; o.y += v1; *p = o;
                } else { // MODE_PROJ
                    float2* p = (float2*)(Cp + (size_t)dest * CC + c);
                    float2 o = *p; o.x += v0; o.y += v1; *p = o;
                }
            }
        }
    }
}

// ---------------------------------------------------------------------------
// Fused windowed attention; reads fp32 qkv, writes hi/lo fp16 output
// ---------------------------------------------------------------------------
__global__ __launch_bounds__(64) void attn_kernel(
    const float* __restrict__ qkv, const float* __restrict__ tbl,
    __half* __restrict__ oh, __half* __restrict__ ol, int shift)
{
    __shared__ float ks[64][32];
    __shared__ float vs[64][32];
    __shared__ float tbl_s[225];
    __shared__ int   rid_s[64];

    int head = blockIdx.x;
    int bw   = blockIdx.y;
    int tid  = threadIdx.x;

    const float* base = qkv + (size_t)bw * NTOK * QKVDIM;
#pragma unroll
    for (int idx = tid; idx < 2048; idx += 64) {
        int m = idx >> 5, d = idx & 31;
        ks[m][d] = base[m * QKVDIM + 192 + head * 32 + d];
        vs[m][d] = base[m * QKVDIM + 384 + head * 32 + d];
    }
    for (int idx = tid; idx < 225; idx += 64)
        tbl_s[idx] = tbl[idx * NHEAD + head];
    {
        int wr = (bw >> 3) & 7, wc = bw & 7;
        int ti = tid >> 3, tj = tid & 7;
        int h = wr * 8 + ti, w = wc * 8 + tj;
        int rh = (h < 56) ? 0 : ((h < 60) ? 1 : 2);
        int rw = (w < 56) ? 0 : ((w < 60) ? 1 : 2);
        rid_s[tid] = rh * 3 + rw;
    }
    __syncthreads();

    int n = tid;
    float qv[32];
    const float* qp = base + n * QKVDIM + head * 32;
#pragma unroll
    for (int d = 0; d < 32; d++) qv[d] = qp[d] * SCALE_Q;

    int ni = n >> 3, nj = n & 7;
    int myid = rid_s[n];

    float s[64];
    float mx = -1e30f;
#pragma unroll
    for (int m = 0; m < 64; m++) {
        float dot = 0.f;
#pragma unroll
        for (int d = 0; d < 32; d += 4) {
            float4 kk = *(const float4*)&ks[m][d];
            dot += qv[d] * kk.x + qv[d + 1] * kk.y + qv[d + 2] * kk.z + qv[d + 3] * kk.w;
        }
        int mi = m >> 3, mj = m & 7;
        float val = dot + tbl_s[(ni - mi + 7) * 15 + (nj - mj + 7)];
        if (shift && rid_s[m] != myid) val -= 100.f;
        s[m] = val;
        mx = fmaxf(mx, val);
    }

    float sum = 0.f;
    float accv[32];
#pragma unroll
    for (int d = 0; d < 32; d++) accv[d] = 0.f;
#pragma unroll
    for (int m = 0; m < 64; m++) {
        float e = __expf(s[m] - mx);
        sum += e;
#pragma unroll
        for (int d = 0; d < 32; d += 4) {
            float4 vv = *(const float4*)&vs[m][d];
            accv[d]     += e * vv.x;
            accv[d + 1] += e * vv.y;
            accv[d + 2] += e * vv.z;
            accv[d + 3] += e * vv.w;
        }
    }
    float inv = 1.f / sum;
    size_t ob = (size_t)(bw * NTOK + n) * CC + head * 32;
#pragma unroll
    for (int d = 0; d < 32; d++) {
        float v = accv[d] * inv;
        __half hh = __float2half(v);
        oh[ob + d] = hh;
        ol[ob + d] = __float2half(v - __half2float(hh));
    }
}

// ---------------------------------------------------------------------------
// Launch
// ---------------------------------------------------------------------------
extern "C" void kernel_launch(void* const* d_in, const int* in_sizes, int n_in,
                              void* d_out, int out_size)
{
    const float* x    = (const float*)d_in[0];
    const float* n1g  = (const float*)d_in[1];
    const float* n1b  = (const float*)d_in[2];
    const float* qkvw = (const float*)d_in[3];
    const float* qkvb = (const float*)d_in[4];
    const float* tbl  = (const float*)d_in[5];
    const float* pw   = (const float*)d_in[6];
    const float* pb   = (const float*)d_in[7];
    const float* n2g  = (const float*)d_in[8];
    const float* n2b  = (const float*)d_in[9];
    const float* f1w  = (const float*)d_in[10];
    const float* f1b  = (const float*)d_in[11];
    const float* f2w  = (const float*)d_in[12];
    const float* f2b  = (const float*)d_in[13];
    float* xo = (float*)d_out;

    __half *ah, *al, *bh, *bl, *wh, *wl;
    float* big;
    cudaGetSymbolAddress((void**)&ah,  g_ah);
    cudaGetSymbolAddress((void**)&al,  g_al);
    cudaGetSymbolAddress((void**)&bh,  g_bh);
    cudaGetSymbolAddress((void**)&bl,  g_bl);
    cudaGetSymbolAddress((void**)&wh,  g_wh);
    cudaGetSymbolAddress((void**)&wl,  g_wl);
    cudaGetSymbolAddress((void**)&big, g_big);

    cudaFuncSetAttribute(gemm_mma<MODE_STORE>,   cudaFuncAttributeMaxDynamicSharedMemorySize, GEMM_SMEM);
    cudaFuncSetAttribute(gemm_mma<MODE_GELU_HL>, cudaFuncAttributeMaxDynamicSharedMemorySize, GEMM_SMEM);
    cudaFuncSetAttribute(gemm_mma<MODE_RESADD>,  cudaFuncAttributeMaxDynamicSharedMemorySize, GEMM_SMEM);
    cudaFuncSetAttribute(gemm_mma<MODE_PROJ>,    cudaFuncAttributeMaxDynamicSharedMemorySize, GEMM_SMEM);

    cudaMemcpyAsync(xo, x, (size_t)MROWS * CC * sizeof(float),
                    cudaMemcpyDeviceToDevice);

    // Convert all weights (both depths) to hi/lo fp16 once per launch
    cvt_kernel<<<(221184 + 255) / 256, 256>>>(qkvw, wh + WOFF_QKV, wl + WOFF_QKV, 221184);
    cvt_kernel<<<(73728  + 255) / 256, 256>>>(pw,   wh + WOFF_PROJ, wl + WOFF_PROJ, 73728);
    cvt_kernel<<<(294912 + 255) / 256, 256>>>(f1w,  wh + WOFF_FC1, wl + WOFF_FC1, 294912);
    cvt_kernel<<<(294912 + 255) / 256, 256>>>(f2w,  wh + WOFF_FC2, wl + WOFF_FC2, 294912);

    for (int dep = 0; dep < 2; dep++) {
        int shift = dep ? 4 : 0;
        const __half* wqh = wh + WOFF_QKV  + (size_t)dep * 110592;
        const __half* wql = wl + WOFF_QKV  + (size_t)dep * 110592;
        const __half* wph = wh + WOFF_PROJ + (size_t)dep * 36864;
        const __half* wpl = wl + WOFF_PROJ + (size_t)dep * 36864;
        const __half* w1h = wh + WOFF_FC1  + (size_t)dep * 147456;
        const __half* w1l = wl + WOFF_FC1  + (size_t)dep * 147456;
        const __half* w2h = wh + WOFF_FC2  + (size_t)dep * 147456;
        const __half* w2l = wl + WOFF_FC2  + (size_t)dep * 147456;

        // LN1 + shift + window partition -> (ah, al)
        ln_kernel<<<MROWS / 8, 256>>>(xo, n1g + dep * CC, n1b + dep * CC, ah, al, shift, 1);

        // QKV GEMM -> big (fp32)
        gemm_mma<MODE_STORE><<<dim3(QKVDIM / 64, MROWS / 128), 256, GEMM_SMEM>>>(
            ah, al, wqh, wql, qkvb + dep * QKVDIM, big, nullptr, nullptr,
            QKVDIM, CC, 0);

        // Attention -> (ah, al)
        attn_kernel<<<dim3(NHEAD, BATCH * NWIN), 64>>>(
            big, tbl + dep * 225 * NHEAD, ah, al, shift);

        // Proj GEMM + window reverse + residual -> xo
        gemm_mma<MODE_PROJ><<<dim3(CC / 64, MROWS / 128), 256, GEMM_SMEM>>>(
            ah, al, wph, wpl, pb + dep * CC, xo, nullptr, nullptr,
            CC, CC, shift);

        // LN2 -> (ah, al)
        ln_kernel<<<MROWS / 8, 256>>>(xo, n2g + dep * CC, n2b + dep * CC, ah, al, 0, 0);

        // FC1 GEMM + GELU -> (bh, bl)
        gemm_mma<MODE_GELU_HL><<<dim3(MLPDIM / 64, MROWS / 128), 256, GEMM_SMEM>>>(
            ah, al, w1h, w1l, f1b + dep * MLPDIM, nullptr, bh, bl,
            MLPDIM, CC, 0);

        // FC2 GEMM + residual -> xo
        gemm_mma<MODE_RESADD><<<dim3(CC / 64, MROWS / 128), 256, GEMM_SMEM>>>(
            bh, bl, w2h, w2l, f2b + dep * CC, xo, nullptr, nullptr,
            CC, MLPDIM, 0);
    }
}